// round 4
// baseline (speedup 1.0000x reference)
#include <cuda_runtime.h>
#include <cuda_bf16.h>
#include <cstdint>

#define Bsz 1024
#define Tsz 256
#define Dsz 128
#define Hsz 64
#define G4  256   // 4*H

// 256 MB scratch for x_proj[b*T + t][g] (NO bias; bias added in recurrence)
__device__ float g_xproj[Bsz * Tsz * G4];

__device__ __forceinline__ uint32_t smem_u32(const void* p) {
    uint32_t a;
    asm("{ .reg .u64 t; cvta.to.shared.u64 t, %1; cvt.u32.u64 %0, t; }"
        : "=r"(a) : "l"(p));
    return a;
}

// ===========================================================================
// Kernel A: x_proj = x @ W_ih^T via legacy tensor cores (mma.sync bf16,
// split hi/lo, 3 passes -> ~fp32 accuracy). M=262144, N=256, K=128.
// 512 CTAs x 512 threads, 4 M-tiles (128 rows) per CTA.
// Warp w computes rows (w&7)*16..+15, cols (w>>3)*128..+127 of the tile.
// ===========================================================================
#define GEMM_CTAS     512
#define TILES_PER_CTA 4
#define TM 128
#define STRB 272                       // smem row stride bytes (136 bf16, conflict-free ldmatrix)
#define A_BYTES (128 * STRB)           // 34816
#define B_BYTES (256 * STRB)           // 69632
#define OFF_AH 0
#define OFF_AL (A_BYTES)
#define OFF_BH (2 * A_BYTES)
#define OFF_BL (2 * A_BYTES + B_BYTES)
#define GEMM_SMEM (2 * A_BYTES + 2 * B_BYTES + 1024)   // 209920

__device__ __forceinline__ void ldsm_x4(uint32_t* r, uint32_t addr) {
    asm volatile("ldmatrix.sync.aligned.m8n8.x4.shared.b16 {%0,%1,%2,%3}, [%4];"
                 : "=r"(r[0]), "=r"(r[1]), "=r"(r[2]), "=r"(r[3]) : "r"(addr));
}

__device__ __forceinline__ void mma16816(float* d, const uint32_t* a,
                                         uint32_t b0, uint32_t b1) {
    asm volatile(
        "mma.sync.aligned.m16n8k16.row.col.f32.bf16.bf16.f32 "
        "{%0,%1,%2,%3}, {%4,%5,%6,%7}, {%8,%9}, {%0,%1,%2,%3};"
        : "+f"(d[0]), "+f"(d[1]), "+f"(d[2]), "+f"(d[3])
        : "r"(a[0]), "r"(a[1]), "r"(a[2]), "r"(a[3]), "r"(b0), "r"(b1));
}

__device__ __forceinline__ void split2(float a, float b, uint32_t& hi, uint32_t& lo) {
    __nv_bfloat16 ah = __float2bfloat16(a);
    __nv_bfloat16 bh = __float2bfloat16(b);
    __nv_bfloat162 h = __halves2bfloat162(ah, bh);
    __nv_bfloat162 l = __floats2bfloat162_rn(a - __bfloat162float(ah),
                                             b - __bfloat162float(bh));
    hi = *(uint32_t*)&h;
    lo = *(uint32_t*)&l;
}

__global__ __launch_bounds__(512, 1) void xproj_tc(
    const float* __restrict__ x,
    const float* __restrict__ Wih)
{
    extern __shared__ char dyn[];
    char* base = (char*)(((uintptr_t)dyn + 1023) & ~(uintptr_t)1023);

    const int tid  = threadIdx.x;
    const int lane = tid & 31;
    const int warp = tid >> 5;
    const int mrow_off = (warp & 7) * 16;    // warp's m offset inside tile
    const int ncol_off = (warp >> 3) * 128;  // warp's n offset

    // ---- convert B (Wih 256x128 fp32 -> bf16 hi/lo smem), once per CTA ----
    {
        const int row  = tid >> 1;
        const int koff = (tid & 1) * 64;
        const float4* src = (const float4*)(Wih + (size_t)row * Dsz + koff);
        char* bh = base + OFF_BH + row * STRB + koff * 2;
        char* bl = base + OFF_BL + row * STRB + koff * 2;
#pragma unroll
        for (int q = 0; q < 16; q++) {
            float4 v = src[q];
            uint32_t h0, l0, h1, l1;
            split2(v.x, v.y, h0, l0);
            split2(v.z, v.w, h1, l1);
            *(uint2*)(bh + q * 8) = make_uint2(h0, h1);
            *(uint2*)(bl + q * 8) = make_uint2(l0, l1);
        }
    }

    const uint32_t sAh = smem_u32(base + OFF_AH);
    const uint32_t sAl = smem_u32(base + OFF_AL);
    const uint32_t sBh = smem_u32(base + OFF_BH);
    const uint32_t sBl = smem_u32(base + OFF_BL);

    // per-lane ldmatrix address offsets
    const uint32_t a_lane = (uint32_t)(mrow_off + (lane & 15)) * STRB + (lane >> 4) * 16;
    const uint32_t b_lane = (uint32_t)(ncol_off + ((lane >> 4) << 3) + (lane & 7)) * STRB
                          + ((lane >> 3) & 1) * 16;

    const int conv_row  = tid >> 2;
    const int conv_koff = (tid & 3) * 32;

    for (int i = 0; i < TILES_PER_CTA; i++) {
        const size_t tile_m = (size_t)(blockIdx.x * TILES_PER_CTA + i) * TM;

        __syncthreads();   // previous tile's mma reads done before overwriting A

        // ---- convert A tile (128x128 fp32 -> bf16 hi/lo smem) ----
        {
            const float4* src = (const float4*)(x + (tile_m + conv_row) * Dsz + conv_koff);
            char* ah = base + OFF_AH + conv_row * STRB + conv_koff * 2;
            char* al = base + OFF_AL + conv_row * STRB + conv_koff * 2;
#pragma unroll
            for (int q = 0; q < 8; q++) {
                float4 v = src[q];
                uint32_t h0, l0, h1, l1;
                split2(v.x, v.y, h0, l0);
                split2(v.z, v.w, h1, l1);
                *(uint2*)(ah + q * 8) = make_uint2(h0, h1);
                *(uint2*)(al + q * 8) = make_uint2(l0, l1);
            }
        }
        __syncthreads();

        float acc[16][4];
#pragma unroll
        for (int j = 0; j < 16; j++)
#pragma unroll
            for (int q = 0; q < 4; q++) acc[j][q] = 0.f;

        // 3 passes: Ah*Bh, Ah*Bl, Al*Bh
#pragma unroll
        for (int pass = 0; pass < 3; pass++) {
            const uint32_t aBase = (pass == 2) ? sAl : sAh;
            const uint32_t bBase = (pass == 1) ? sBl : sBh;
#pragma unroll
            for (int ks = 0; ks < 8; ks++) {
                uint32_t ra[4];
                ldsm_x4(ra, aBase + a_lane + ks * 32);
#pragma unroll
                for (int j = 0; j < 8; j++) {
                    uint32_t rb[4];
                    ldsm_x4(rb, bBase + b_lane + j * (16 * STRB) + ks * 32);
                    mma16816(acc[2 * j],     ra, rb[0], rb[1]);
                    mma16816(acc[2 * j + 1], ra, rb[2], rb[3]);
                }
            }
        }

        // ---- store: thread holds D[g][2tc..], D[g+8][2tc..] per 8-col tile ----
        const int g  = lane >> 2;
        const int tc = lane & 3;
        float* dst = g_xproj + (tile_m + mrow_off + g) * G4 + ncol_off + 2 * tc;
#pragma unroll
        for (int j = 0; j < 16; j++) {
            *(float2*)(dst + j * 8)          = make_float2(acc[j][0], acc[j][1]);
            *(float2*)(dst + 8 * G4 + j * 8) = make_float2(acc[j][2], acc[j][3]);
        }
    }
}

// ===========================================================================
// Kernel B: LSTM recurrence + fused MLP head (known-good R2 structure,
// bias folded here since the GEMM no longer adds it).
// 256 blocks x 256 threads, NB=4 rows/block, 2 CTAs/SM.
// ===========================================================================
#define NB 4

__device__ __forceinline__ float sigm(float v) {
    return __fdividef(1.f, 1.f + __expf(-v));
}
__device__ __forceinline__ float tanh_f(float v) {
    return 1.f - __fdividef(2.f, __expf(2.f * v) + 1.f);
}

__global__ __launch_bounds__(256, 2) void lstm_rec(
    const float* __restrict__ Whh,
    const float* __restrict__ bih, const float* __restrict__ bhh,
    const float* __restrict__ W1, const float* __restrict__ b1,
    const float* __restrict__ W2, const float* __restrict__ b2,
    float* __restrict__ out)
{
    __shared__ __align__(16) float h_sh[NB][Hsz];
    __shared__ float gs[NB][G4];

    const int tid = threadIdx.x;     // gate index g (0..255)
    const int r0  = blockIdx.x * NB;

    float w[Hsz];
#pragma unroll
    for (int k = 0; k < Hsz; k++) w[k] = Whh[tid * Hsz + k];
    const float bias = bih[tid] + bhh[tid];

    for (int i = tid; i < NB * Hsz; i += 256) ((float*)h_sh)[i] = 0.f;

    const int rr = tid >> 6;
    const int jj = tid & 63;
    float c = 0.f;

    float xp[NB], xn[NB];
#pragma unroll
    for (int r = 0; r < NB; r++)
        xp[r] = g_xproj[((size_t)(r0 + r) * Tsz) * G4 + tid];

    __syncthreads();

    for (int t = 0; t < Tsz; t++) {
        const int tn = (t + 1 < Tsz) ? t + 1 : t;
#pragma unroll
        for (int r = 0; r < NB; r++)
            xn[r] = g_xproj[((size_t)(r0 + r) * Tsz + tn) * G4 + tid];

        float acc[NB];
#pragma unroll
        for (int r = 0; r < NB; r++) acc[r] = xp[r] + bias;

#pragma unroll
        for (int k4 = 0; k4 < 16; k4++) {
#pragma unroll
            for (int r = 0; r < NB; r++) {
                float4 h4 = *(const float4*)&h_sh[r][k4 * 4];
                acc[r] += w[k4 * 4 + 0] * h4.x;
                acc[r] += w[k4 * 4 + 1] * h4.y;
                acc[r] += w[k4 * 4 + 2] * h4.z;
                acc[r] += w[k4 * 4 + 3] * h4.w;
            }
        }

#pragma unroll
        for (int r = 0; r < NB; r++) gs[r][tid] = acc[r];
        __syncthreads();

        {
            float ig = sigm(gs[rr][jj]);
            float fg = sigm(gs[rr][64 + jj]);
            float gg = tanh_f(gs[rr][128 + jj]);
            float og = sigm(gs[rr][192 + jj]);
            c = fg * c + ig * gg;
            h_sh[rr][jj] = og * tanh_f(c);
        }

#pragma unroll
        for (int r = 0; r < NB; r++) xp[r] = xn[r];
        __syncthreads();
    }

    const int wid  = tid >> 5;
    const int lane = tid & 31;
    if (wid < NB) {
        float y1 = b1[lane];
#pragma unroll
        for (int k = 0; k < Hsz; k++) y1 += W1[lane * Hsz + k] * h_sh[wid][k];
        y1 = fmaxf(y1, 0.f);
        float z = y1 * W2[lane];
#pragma unroll
        for (int off = 16; off > 0; off >>= 1) z += __shfl_down_sync(0xffffffffu, z, off);
        if (lane == 0) out[r0 + wid] = sigm(z + b2[0]);
    }
}

// ===========================================================================
extern "C" void kernel_launch(void* const* d_in, const int* in_sizes, int n_in,
                              void* d_out, int out_size)
{
    const float* x   = (const float*)d_in[0];
    const float* Wih = (const float*)d_in[1];
    const float* Whh = (const float*)d_in[2];
    const float* bih = (const float*)d_in[3];
    const float* bhh = (const float*)d_in[4];
    const float* W1  = (const float*)d_in[5];
    const float* b1  = (const float*)d_in[6];
    const float* W2  = (const float*)d_in[7];
    const float* b2  = (const float*)d_in[8];
    float* out = (float*)d_out;

    static bool attr_set = false;
    if (!attr_set) {
        cudaFuncSetAttribute(xproj_tc, cudaFuncAttributeMaxDynamicSharedMemorySize, GEMM_SMEM);
        attr_set = true;
    }
    xproj_tc<<<GEMM_CTAS, 512, GEMM_SMEM>>>(x, Wih);
    lstm_rec<<<Bsz / NB, 256>>>(Whh, bih, bhh, W1, b1, W2, b2, out);
}

// round 6
// speedup vs baseline: 1.7550x; 1.7550x over previous
#include <cuda_runtime.h>
#include <cuda_fp16.h>
#include <cstdint>

#define Bsz 1024
#define Tsz 256
#define Dsz 128
#define Hsz 64
#define G4  256   // 4*H

// 256 MB scratch, layout [t][b][g]  (recurrence-friendly: step t reads a 1MB slab)
__device__ float g_xproj[Tsz * Bsz * G4];

__device__ __forceinline__ uint32_t smem_u32(const void* p) {
    uint32_t a;
    asm("{ .reg .u64 t; cvta.to.shared.u64 t, %1; cvt.u32.u64 %0, t; }"
        : "=r"(a) : "l"(p));
    return a;
}

// ===========================================================================
// Kernel A: x_proj = x @ W_ih^T, single-pass fp16 HMMA, fp32 accumulate.
// M=262144, N=256, K=128. 512 CTAs x 512 threads, 4 M-tiles (128 rows)/CTA.
// Warp w: rows (w&7)*16..+15, cols (w>>3)*128..+127 of the tile.
// ===========================================================================
#define GEMM_CTAS     512
#define TILES_PER_CTA 4
#define TM 128
#define STRB 272                     // smem row stride bytes (conflict-free ldmatrix)
#define A_BYTES (128 * STRB)
#define B_BYTES (256 * STRB)
#define OFF_A 0
#define OFF_B (A_BYTES)
#define GEMM_SMEM (A_BYTES + B_BYTES + 1024)

__device__ __forceinline__ void ldsm_x4(uint32_t* r, uint32_t addr) {
    asm volatile("ldmatrix.sync.aligned.m8n8.x4.shared.b16 {%0,%1,%2,%3}, [%4];"
                 : "=r"(r[0]), "=r"(r[1]), "=r"(r[2]), "=r"(r[3]) : "r"(addr));
}

__device__ __forceinline__ void mma16816(float* d, const uint32_t* a,
                                         uint32_t b0, uint32_t b1) {
    asm volatile(
        "mma.sync.aligned.m16n8k16.row.col.f32.f16.f16.f32 "
        "{%0,%1,%2,%3}, {%4,%5,%6,%7}, {%8,%9}, {%0,%1,%2,%3};"
        : "+f"(d[0]), "+f"(d[1]), "+f"(d[2]), "+f"(d[3])
        : "r"(a[0]), "r"(a[1]), "r"(a[2]), "r"(a[3]), "r"(b0), "r"(b1));
}

__device__ __forceinline__ uint32_t h2(float a, float b) {
    __half2 h = __floats2half2_rn(a, b);
    return *(uint32_t*)&h;
}

__global__ __launch_bounds__(512, 1) void xproj_tc(
    const float* __restrict__ x,
    const float* __restrict__ Wih)
{
    extern __shared__ char dyn[];
    char* base = (char*)(((uintptr_t)dyn + 1023) & ~(uintptr_t)1023);

    const int tid  = threadIdx.x;
    const int lane = tid & 31;
    const int warp = tid >> 5;
    const int mrow_off = (warp & 7) * 16;
    const int ncol_off = (warp >> 3) * 128;

    // ---- convert B (Wih 256x128 fp32 -> fp16 smem), once per CTA ----
    {
        const int row  = tid >> 1;
        const int koff = (tid & 1) * 64;
        const float4* src = (const float4*)(Wih + (size_t)row * Dsz + koff);
        char* bh = base + OFF_B + row * STRB + koff * 2;
#pragma unroll
        for (int q = 0; q < 16; q++) {
            float4 v = src[q];
            *(uint2*)(bh + q * 8) = make_uint2(h2(v.x, v.y), h2(v.z, v.w));
        }
    }

    const uint32_t sA = smem_u32(base + OFF_A);
    const uint32_t sB = smem_u32(base + OFF_B);

    const uint32_t a_lane = (uint32_t)(mrow_off + (lane & 15)) * STRB + (lane >> 4) * 16;
    const uint32_t b_lane = (uint32_t)(ncol_off + ((lane >> 4) << 3) + (lane & 7)) * STRB
                          + ((lane >> 3) & 1) * 16;

    const int conv_row  = tid >> 2;
    const int conv_koff = (tid & 3) * 32;

    for (int i = 0; i < TILES_PER_CTA; i++) {
        const size_t tile_m = (size_t)(blockIdx.x * TILES_PER_CTA + i) * TM;

        __syncthreads();   // previous tile's mma reads done before overwriting A

        // ---- convert A tile (128x128 fp32 -> fp16 smem) ----
        {
            const float4* src = (const float4*)(x + (tile_m + conv_row) * Dsz + conv_koff);
            char* ah = base + OFF_A + conv_row * STRB + conv_koff * 2;
#pragma unroll
            for (int q = 0; q < 8; q++) {
                float4 v = src[q];
                *(uint2*)(ah + q * 8) = make_uint2(h2(v.x, v.y), h2(v.z, v.w));
            }
        }
        __syncthreads();

        float acc[16][4];
#pragma unroll
        for (int j = 0; j < 16; j++)
#pragma unroll
            for (int q = 0; q < 4; q++) acc[j][q] = 0.f;

#pragma unroll
        for (int ks = 0; ks < 8; ks++) {
            uint32_t ra[4];
            ldsm_x4(ra, sA + a_lane + ks * 32);
#pragma unroll
            for (int j = 0; j < 8; j++) {
                uint32_t rb[4];
                ldsm_x4(rb, sB + b_lane + j * (16 * STRB) + ks * 32);
                mma16816(acc[2 * j],     ra, rb[0], rb[1]);
                mma16816(acc[2 * j + 1], ra, rb[2], rb[3]);
            }
        }

        // ---- store into [t][b][g]: m = b*Tsz + t  (Tsz=256 so t = m&255) ----
        const int g  = lane >> 2;
        const int tc = lane & 3;
        const size_t m0 = tile_m + mrow_off + g;       // row m (and m+8)
        const size_t t0 = m0 & 255, b0 = m0 >> 8;
        float* dst0 = g_xproj + (t0 * Bsz + b0) * G4 + ncol_off + 2 * tc;
        float* dst1 = dst0 + 8 * (size_t)Bsz * G4;     // t0+8, same b (tile never crosses b)
#pragma unroll
        for (int j = 0; j < 16; j++) {
            *(float2*)(dst0 + j * 8) = make_float2(acc[j][0], acc[j][1]);
            *(float2*)(dst1 + j * 8) = make_float2(acc[j][2], acc[j][3]);
        }
    }
}

// ===========================================================================
// Kernel B: LSTM recurrence, unit-major mapping, intra-warp gate exchange,
// ONE __syncthreads per step. 256 blocks x 256 threads, NB=4, 2 CTAs/SM.
// warp w owns units j in [8w, 8w+8); lane = (j_local<<2) | gate_idx.
// Thread computes gate row g = gate_idx*64 + j across NB rows (W row in regs),
// then pointwise for row (gate_idx) of unit j.
// ===========================================================================
#define NB  4
#define HP  72    // padded h row (floats): banks (8*buf_r + j) conflict-free
#define GSR 296   // gs stride per r (floats): read banks (8gi + 8k + j) conflict-free

__device__ __forceinline__ float sigm(float v) {
    return __fdividef(1.f, 1.f + __expf(-v));
}
__device__ __forceinline__ float tanh_f(float v) {
    return 1.f - __fdividef(2.f, __expf(2.f * v) + 1.f);
}

__global__ __launch_bounds__(256, 2) void lstm_rec(
    const float* __restrict__ Whh,
    const float* __restrict__ bih, const float* __restrict__ bhh,
    const float* __restrict__ W1, const float* __restrict__ b1,
    const float* __restrict__ W2, const float* __restrict__ b2,
    float* __restrict__ out)
{
    __shared__ __align__(16) float h_sh[2][NB][HP];
    __shared__ float gs[NB * GSR];

    const int tid = threadIdx.x;
    const int wrp = tid >> 5;
    const int ln  = tid & 31;
    const int jl  = ln >> 2;
    const int gi  = ln & 3;              // gate idx AND (for pointwise) row idx
    const int j   = 8 * wrp + jl;        // unit 0..63
    const int g   = gi * 64 + j;         // gate row in [0,256)
    const int r0  = blockIdx.x * NB;

    float w[Hsz];
#pragma unroll
    for (int k = 0; k < Hsz; k++) w[k] = Whh[g * Hsz + k];
    const float bias = bih[g] + bhh[g];

    for (int i = tid; i < 2 * NB * HP; i += 256) ((float*)h_sh)[i] = 0.f;

    float c = 0.f;

    float xp[NB], xn[NB];
#pragma unroll
    for (int r = 0; r < NB; r++)
        xp[r] = g_xproj[(size_t)(r0 + r) * G4 + g];   // t = 0

    __syncthreads();

    int buf = 0;
    for (int t = 0; t < Tsz; t++) {
        const int tn = (t + 1 < Tsz) ? t + 1 : t;
#pragma unroll
        for (int r = 0; r < NB; r++)
            xn[r] = g_xproj[((size_t)tn * Bsz + r0 + r) * G4 + g];

        float acc[NB];
#pragma unroll
        for (int r = 0; r < NB; r++) acc[r] = xp[r] + bias;

#pragma unroll
        for (int k4 = 0; k4 < 16; k4++) {
#pragma unroll
            for (int r = 0; r < NB; r++) {
                float4 h4 = *(const float4*)&h_sh[buf][r][k4 * 4];
                acc[r] += w[k4 * 4 + 0] * h4.x;
                acc[r] += w[k4 * 4 + 1] * h4.y;
                acc[r] += w[k4 * 4 + 2] * h4.z;
                acc[r] += w[k4 * 4 + 3] * h4.w;
            }
        }

        // stage gates: cell (r, gate gi, unit j) -> gs[r*GSR + gi*72 + j]
#pragma unroll
        for (int r = 0; r < NB; r++) gs[r * GSR + gi * 72 + j] = acc[r];
        __syncwarp();

        // pointwise for row gi, unit j: gates k=0..3 at gs[gi*GSR + k*72 + j]
        {
            float vi = sigm(gs[gi * GSR + 0 * 72 + j]);
            float vf = sigm(gs[gi * GSR + 1 * 72 + j]);
            float vg = tanh_f(gs[gi * GSR + 2 * 72 + j]);
            float vo = sigm(gs[gi * GSR + 3 * 72 + j]);
            c = vf * c + vi * vg;
            h_sh[buf ^ 1][gi][j] = vo * tanh_f(c);
        }

#pragma unroll
        for (int r = 0; r < NB; r++) xp[r] = xn[r];
        __syncthreads();
        buf ^= 1;
    }

    // Fused head: warp wid (<NB) handles row r0+wid; lane = layer-1 unit
    const int lane = tid & 31;
    if (wrp < NB) {
        float y1 = b1[lane];
#pragma unroll
        for (int k = 0; k < Hsz; k++) y1 += W1[lane * Hsz + k] * h_sh[buf][wrp][k];
        y1 = fmaxf(y1, 0.f);
        float z = y1 * W2[lane];
#pragma unroll
        for (int off = 16; off > 0; off >>= 1) z += __shfl_down_sync(0xffffffffu, z, off);
        if (lane == 0) out[r0 + wrp] = sigm(z + b2[0]);
    }
}

// ===========================================================================
extern "C" void kernel_launch(void* const* d_in, const int* in_sizes, int n_in,
                              void* d_out, int out_size)
{
    const float* x   = (const float*)d_in[0];
    const float* Wih = (const float*)d_in[1];
    const float* Whh = (const float*)d_in[2];
    const float* bih = (const float*)d_in[3];
    const float* bhh = (const float*)d_in[4];
    const float* W1  = (const float*)d_in[5];
    const float* b1  = (const float*)d_in[6];
    const float* W2  = (const float*)d_in[7];
    const float* b2  = (const float*)d_in[8];
    float* out = (float*)d_out;

    static bool attr_set = false;
    if (!attr_set) {
        cudaFuncSetAttribute(xproj_tc, cudaFuncAttributeMaxDynamicSharedMemorySize, GEMM_SMEM);
        attr_set = true;
    }
    xproj_tc<<<GEMM_CTAS, 512, GEMM_SMEM>>>(x, Wih);
    lstm_rec<<<Bsz / NB, 256>>>(Whh, bih, bhh, W1, b1, W2, b2, out);
}

// round 10
// speedup vs baseline: 1.9532x; 1.1130x over previous
#include <cuda_runtime.h>
#include <cuda_fp16.h>
#include <cstdint>

#define Bsz 1024
#define Tsz 256
#define Dsz 128
#define Hsz 64
#define G4  256   // 4*H

// 256 MB scratch, layout [t][b][g]  (recurrence-friendly: step t reads a 1MB slab)
__device__ float g_xproj[Tsz * Bsz * G4];

__device__ __forceinline__ uint32_t smem_u32(const void* p) {
    uint32_t a;
    asm("{ .reg .u64 t; cvta.to.shared.u64 t, %1; cvt.u32.u64 %0, t; }"
        : "=r"(a) : "l"(p));
    return a;
}

__device__ __forceinline__ void ldsm_x4(uint32_t* r, uint32_t addr) {
    asm volatile("ldmatrix.sync.aligned.m8n8.x4.shared.b16 {%0,%1,%2,%3}, [%4];"
                 : "=r"(r[0]), "=r"(r[1]), "=r"(r[2]), "=r"(r[3]) : "r"(addr));
}

__device__ __forceinline__ void mma16816(float* d, const uint32_t* a,
                                         uint32_t b0, uint32_t b1) {
    asm volatile(
        "mma.sync.aligned.m16n8k16.row.col.f32.f16.f16.f32 "
        "{%0,%1,%2,%3}, {%4,%5,%6,%7}, {%8,%9}, {%0,%1,%2,%3};"
        : "+f"(d[0]), "+f"(d[1]), "+f"(d[2]), "+f"(d[3])
        : "r"(a[0]), "r"(a[1]), "r"(a[2]), "r"(a[3]), "r"(b0), "r"(b1));
}

__device__ __forceinline__ uint32_t h2(float a, float b) {
    __half2 h = __floats2half2_rn(a, b);
    return *(uint32_t*)&h;
}

// ===========================================================================
// Kernel A: x_proj = x @ W_ih^T, single-pass fp16 HMMA, fp32 accumulate.
// (unchanged — at the legacy-HMMA roofline)
// ===========================================================================
#define GEMM_CTAS     512
#define TILES_PER_CTA 4
#define TM 128
#define STRB 272
#define A_BYTES (128 * STRB)
#define B_BYTES (256 * STRB)
#define OFF_A 0
#define OFF_B (A_BYTES)
#define GEMM_SMEM (A_BYTES + B_BYTES + 1024)

__global__ __launch_bounds__(512, 1) void xproj_tc(
    const float* __restrict__ x,
    const float* __restrict__ Wih)
{
    extern __shared__ char dyn[];
    char* base = (char*)(((uintptr_t)dyn + 1023) & ~(uintptr_t)1023);

    const int tid  = threadIdx.x;
    const int lane = tid & 31;
    const int warp = tid >> 5;
    const int mrow_off = (warp & 7) * 16;
    const int ncol_off = (warp >> 3) * 128;

    {
        const int row  = tid >> 1;
        const int koff = (tid & 1) * 64;
        const float4* src = (const float4*)(Wih + (size_t)row * Dsz + koff);
        char* bh = base + OFF_B + row * STRB + koff * 2;
#pragma unroll
        for (int q = 0; q < 16; q++) {
            float4 v = src[q];
            *(uint2*)(bh + q * 8) = make_uint2(h2(v.x, v.y), h2(v.z, v.w));
        }
    }

    const uint32_t sA = smem_u32(base + OFF_A);
    const uint32_t sB = smem_u32(base + OFF_B);

    const uint32_t a_lane = (uint32_t)(mrow_off + (lane & 15)) * STRB + (lane >> 4) * 16;
    const uint32_t b_lane = (uint32_t)(ncol_off + ((lane >> 4) << 3) + (lane & 7)) * STRB
                          + ((lane >> 3) & 1) * 16;

    const int conv_row  = tid >> 2;
    const int conv_koff = (tid & 3) * 32;

    for (int i = 0; i < TILES_PER_CTA; i++) {
        const size_t tile_m = (size_t)(blockIdx.x * TILES_PER_CTA + i) * TM;

        __syncthreads();

        {
            const float4* src = (const float4*)(x + (tile_m + conv_row) * Dsz + conv_koff);
            char* ah = base + OFF_A + conv_row * STRB + conv_koff * 2;
#pragma unroll
            for (int q = 0; q < 8; q++) {
                float4 v = src[q];
                *(uint2*)(ah + q * 8) = make_uint2(h2(v.x, v.y), h2(v.z, v.w));
            }
        }
        __syncthreads();

        float acc[16][4];
#pragma unroll
        for (int j = 0; j < 16; j++)
#pragma unroll
            for (int q = 0; q < 4; q++) acc[j][q] = 0.f;

#pragma unroll
        for (int ks = 0; ks < 8; ks++) {
            uint32_t ra[4];
            ldsm_x4(ra, sA + a_lane + ks * 32);
#pragma unroll
            for (int j = 0; j < 8; j++) {
                uint32_t rb[4];
                ldsm_x4(rb, sB + b_lane + j * (16 * STRB) + ks * 32);
                mma16816(acc[2 * j],     ra, rb[0], rb[1]);
                mma16816(acc[2 * j + 1], ra, rb[2], rb[3]);
            }
        }

        const int g  = lane >> 2;
        const int tc = lane & 3;
        const size_t m0 = tile_m + mrow_off + g;
        const size_t t0 = m0 & 255, b0 = m0 >> 8;
        float* dst0 = g_xproj + (t0 * Bsz + b0) * G4 + ncol_off + 2 * tc;
        float* dst1 = dst0 + 8 * (size_t)Bsz * G4;
#pragma unroll
        for (int j = 0; j < 16; j++) {
            *(float2*)(dst0 + j * 8) = make_float2(acc[j][0], acc[j][1]);
            *(float2*)(dst1 + j * 8) = make_float2(acc[j][2], acc[j][3]);
        }
    }
}

// ===========================================================================
// Kernel B: LSTM recurrence on tensor cores.
// 64 blocks x 512 threads (16 warps). Block owns 16 batch rows.
// Warp w owns gates [16w, 16w+16): W_hh fragments live in 16 registers.
// Per step: 4 A-ldsm (h fp16) + 8 mma + smem gate exchange + pointwise.
// h carried as fp16 between steps (fp32 c state in registers).
// HSTR row stride = 144 bytes: multiple of 16 (LDSM alignment) with the same
// 4-bank per-row shift as the GEMM's 272-byte stride (conflict-free).
// ===========================================================================
#define RB   16     // batch rows per block
#define HSTR 72     // half stride of hA / WhhS rows (144 B)
#define GSTR 264    // float stride of gs rows (8-bank shift: conflict-free)

// static smem: [0,2304) hA ; [2304, 2304+36864) WhhS staging (reused as gs 16896B)
#define SM_HA    0
#define SM_OVL   (RB * HSTR * 2)             // 2304
#define SM_TOTAL (SM_OVL + 256 * HSTR * 2)   // 39168

__device__ __forceinline__ float sigm(float v) {
    return __fdividef(1.f, 1.f + __expf(-v));
}
__device__ __forceinline__ float tanh_f(float v) {
    return 1.f - __fdividef(2.f, __expf(2.f * v) + 1.f);
}

__global__ __launch_bounds__(512, 1) void lstm_rec_tc(
    const float* __restrict__ Whh,
    const float* __restrict__ bih, const float* __restrict__ bhh,
    const float* __restrict__ W1, const float* __restrict__ b1,
    const float* __restrict__ W2, const float* __restrict__ b2,
    float* __restrict__ out)
{
    __shared__ __align__(16) char sm[SM_TOTAL];
    __half* hA  = (__half*)(sm + SM_HA);             // [RB][HSTR]
    __half* WhS = (__half*)(sm + SM_OVL);            // [256][HSTR] staging
    float*  gs  = (float*)(sm + SM_OVL);             // [RB][GSTR] (after preload)

    const int tid  = threadIdx.x;
    const int lane = tid & 31;
    const int w    = tid >> 5;          // warp 0..15 -> gates 16w..16w+15
    const int r0   = blockIdx.x * RB;

    // ---- stage Whh fp32 -> fp16 smem (gate-major, k contiguous) ----
    {
        const int gg   = tid >> 1;
        const int koff = (tid & 1) * 32;
        const float4* src = (const float4*)(Whh + (size_t)gg * Hsz + koff);
        __half* dst = WhS + gg * HSTR + koff;
#pragma unroll
        for (int q = 0; q < 8; q++) {
            float4 v = src[q];
            *(uint2*)(dst + q * 4) = make_uint2(h2(v.x, v.y), h2(v.z, v.w));
        }
    }
    __syncthreads();

    // ---- preload B fragments (W_hh) into registers: 4 k-tiles x 4 regs ----
    uint32_t rbf[4][4];
    {
        const uint32_t sW = smem_u32(WhS);
        const uint32_t b_lane = (uint32_t)(16 * w + ((lane >> 4) << 3) + (lane & 7)) * (HSTR * 2)
                              + ((lane >> 3) & 1) * 16;
#pragma unroll
        for (int kt = 0; kt < 4; kt++) ldsm_x4(rbf[kt], sW + b_lane + kt * 32);
    }
    __syncthreads();   // staging may now be reused as gs

    // ---- zero hA ----
    for (int i = tid; i < RB * Hsz; i += 512) hA[(i >> 6) * HSTR + (i & 63)] = __float2half(0.f);

    // ---- per-thread fragment coords ----
    const int rA  = lane >> 2;               // rows rA, rA+8
    const int gB0 = 16 * w + 2 * (lane & 3); // n-tile 0 gate pair; n-tile 1 = +8

    // bias fragments
    float2 biasv[2];
#pragma unroll
    for (int nt = 0; nt < 2; nt++) {
        int g = gB0 + nt * 8;
        biasv[nt] = make_float2(bih[g] + bhh[g], bih[g + 1] + bhh[g + 1]);
    }

    // xproj fragment pointers: [(t*Bsz + b)*G4 + g]
    const size_t baseA0 = (size_t)(r0 + rA) * G4 + gB0;
    const size_t baseB0 = (size_t)(r0 + rA + 8) * G4 + gB0;
    const size_t tstep  = (size_t)Bsz * G4;

    float2 xpA[2], xpB[2], xnA[2], xnB[2];
#pragma unroll
    for (int nt = 0; nt < 2; nt++) {
        xpA[nt] = *(const float2*)(g_xproj + baseA0 + nt * 8);
        xpB[nt] = *(const float2*)(g_xproj + baseB0 + nt * 8);
    }

    // pointwise cell coords: cells (pr0, pj) and (pr0+8, pj)
    const int pr0 = tid >> 6;            // 0..7
    const int pj  = tid & 63;            // unit
    float c0 = 0.f, c1 = 0.f;

    const uint32_t sHA    = smem_u32(hA);
    const uint32_t a_lane = (uint32_t)(lane & 15) * (HSTR * 2) + (lane >> 4) * 16;

    __syncthreads();

    for (int t = 0; t < Tsz; t++) {
        // prefetch next step's xproj fragments
        const size_t tn = (size_t)((t + 1 < Tsz) ? t + 1 : t) * tstep;
#pragma unroll
        for (int nt = 0; nt < 2; nt++) {
            xnA[nt] = *(const float2*)(g_xproj + tn + baseA0 + nt * 8);
            xnB[nt] = *(const float2*)(g_xproj + tn + baseB0 + nt * 8);
        }

        // acc init = bias + xproj
        float acc[2][4];
#pragma unroll
        for (int nt = 0; nt < 2; nt++) {
            acc[nt][0] = biasv[nt].x + xpA[nt].x;
            acc[nt][1] = biasv[nt].y + xpA[nt].y;
            acc[nt][2] = biasv[nt].x + xpB[nt].x;
            acc[nt][3] = biasv[nt].y + xpB[nt].y;
        }

        // matvec: 4 k-tiles x 2 n-tiles
#pragma unroll
        for (int kt = 0; kt < 4; kt++) {
            uint32_t ra[4];
            ldsm_x4(ra, sHA + a_lane + kt * 32);
            mma16816(acc[0], ra, rbf[kt][0], rbf[kt][1]);
            mma16816(acc[1], ra, rbf[kt][2], rbf[kt][3]);
        }

        // gate exchange
#pragma unroll
        for (int nt = 0; nt < 2; nt++) {
            *(float2*)&gs[rA * GSTR + gB0 + nt * 8]       = make_float2(acc[nt][0], acc[nt][1]);
            *(float2*)&gs[(rA + 8) * GSTR + gB0 + nt * 8] = make_float2(acc[nt][2], acc[nt][3]);
        }
        __syncthreads();

        // pointwise: cell (pr0, pj) and (pr0+8, pj)
        {
            float vi = sigm(gs[pr0 * GSTR + pj]);
            float vf = sigm(gs[pr0 * GSTR + 64 + pj]);
            float vg = tanh_f(gs[pr0 * GSTR + 128 + pj]);
            float vo = sigm(gs[pr0 * GSTR + 192 + pj]);
            c0 = vf * c0 + vi * vg;
            hA[pr0 * HSTR + pj] = __float2half(vo * tanh_f(c0));
        }
        {
            const int pr1 = pr0 + 8;
            float vi = sigm(gs[pr1 * GSTR + pj]);
            float vf = sigm(gs[pr1 * GSTR + 64 + pj]);
            float vg = tanh_f(gs[pr1 * GSTR + 128 + pj]);
            float vo = sigm(gs[pr1 * GSTR + 192 + pj]);
            c1 = vf * c1 + vi * vg;
            hA[pr1 * HSTR + pj] = __float2half(vo * tanh_f(c1));
        }

#pragma unroll
        for (int nt = 0; nt < 2; nt++) { xpA[nt] = xnA[nt]; xpB[nt] = xnB[nt]; }
        __syncthreads();
    }

    // ---- fused head: warp w handles batch row r0 + w ----
    {
        float y1 = b1[lane];
#pragma unroll
        for (int k = 0; k < Hsz; k++)
            y1 += W1[lane * Hsz + k] * __half2float(hA[w * HSTR + k]);
        y1 = fmaxf(y1, 0.f);
        float z = y1 * W2[lane];
#pragma unroll
        for (int off = 16; off > 0; off >>= 1) z += __shfl_down_sync(0xffffffffu, z, off);
        if (lane == 0) out[r0 + w] = sigm(z + b2[0]);
    }
}

// ===========================================================================
extern "C" void kernel_launch(void* const* d_in, const int* in_sizes, int n_in,
                              void* d_out, int out_size)
{
    const float* x   = (const float*)d_in[0];
    const float* Wih = (const float*)d_in[1];
    const float* Whh = (const float*)d_in[2];
    const float* bih = (const float*)d_in[3];
    const float* bhh = (const float*)d_in[4];
    const float* W1  = (const float*)d_in[5];
    const float* b1  = (const float*)d_in[6];
    const float* W2  = (const float*)d_in[7];
    const float* b2  = (const float*)d_in[8];
    float* out = (float*)d_out;

    static bool attr_set = false;
    if (!attr_set) {
        cudaFuncSetAttribute(xproj_tc, cudaFuncAttributeMaxDynamicSharedMemorySize, GEMM_SMEM);
        attr_set = true;
    }
    xproj_tc<<<GEMM_CTAS, 512, GEMM_SMEM>>>(x, Wih);
    lstm_rec_tc<<<Bsz / RB, 512>>>(Whh, bih, bhh, W1, b1, W2, b2, out);
}

// round 11
// speedup vs baseline: 2.4562x; 1.2575x over previous
#include <cuda_runtime.h>
#include <cuda_fp16.h>
#include <cstdint>

#define Bsz 1024
#define Tsz 256
#define Dsz 128
#define Hsz 64
#define G4  256   // 4*H

// 256 MB scratch, layout [t][b][g]
__device__ float g_xproj[Tsz * Bsz * G4];

__device__ __forceinline__ uint32_t smem_u32(const void* p) {
    uint32_t a;
    asm("{ .reg .u64 t; cvta.to.shared.u64 t, %1; cvt.u32.u64 %0, t; }"
        : "=r"(a) : "l"(p));
    return a;
}

__device__ __forceinline__ void ldsm_x4(uint32_t* r, uint32_t addr) {
    asm volatile("ldmatrix.sync.aligned.m8n8.x4.shared.b16 {%0,%1,%2,%3}, [%4];"
                 : "=r"(r[0]), "=r"(r[1]), "=r"(r[2]), "=r"(r[3]) : "r"(addr));
}

__device__ __forceinline__ void mma16816(float* d, const uint32_t* a,
                                         uint32_t b0, uint32_t b1) {
    asm volatile(
        "mma.sync.aligned.m16n8k16.row.col.f32.f16.f16.f32 "
        "{%0,%1,%2,%3}, {%4,%5,%6,%7}, {%8,%9}, {%0,%1,%2,%3};"
        : "+f"(d[0]), "+f"(d[1]), "+f"(d[2]), "+f"(d[3])
        : "r"(a[0]), "r"(a[1]), "r"(a[2]), "r"(a[3]), "r"(b0), "r"(b1));
}

__device__ __forceinline__ uint32_t h2(float a, float b) {
    __half2 h = __floats2half2_rn(a, b);
    return *(uint32_t*)&h;
}

// ===========================================================================
// Kernel A: x_proj = x @ W_ih^T, single-pass fp16 HMMA (unchanged; at roofline)
// ===========================================================================
#define GEMM_CTAS     512
#define TILES_PER_CTA 4
#define TM 128
#define STRB 272
#define A_BYTES (128 * STRB)
#define B_BYTES (256 * STRB)
#define OFF_A 0
#define OFF_B (A_BYTES)
#define GEMM_SMEM (A_BYTES + B_BYTES + 1024)

__global__ __launch_bounds__(512, 1) void xproj_tc(
    const float* __restrict__ x,
    const float* __restrict__ Wih)
{
    extern __shared__ char dyn[];
    char* base = (char*)(((uintptr_t)dyn + 1023) & ~(uintptr_t)1023);

    const int tid  = threadIdx.x;
    const int lane = tid & 31;
    const int warp = tid >> 5;
    const int mrow_off = (warp & 7) * 16;
    const int ncol_off = (warp >> 3) * 128;

    {
        const int row  = tid >> 1;
        const int koff = (tid & 1) * 64;
        const float4* src = (const float4*)(Wih + (size_t)row * Dsz + koff);
        char* bh = base + OFF_B + row * STRB + koff * 2;
#pragma unroll
        for (int q = 0; q < 16; q++) {
            float4 v = src[q];
            *(uint2*)(bh + q * 8) = make_uint2(h2(v.x, v.y), h2(v.z, v.w));
        }
    }

    const uint32_t sA = smem_u32(base + OFF_A);
    const uint32_t sB = smem_u32(base + OFF_B);

    const uint32_t a_lane = (uint32_t)(mrow_off + (lane & 15)) * STRB + (lane >> 4) * 16;
    const uint32_t b_lane = (uint32_t)(ncol_off + ((lane >> 4) << 3) + (lane & 7)) * STRB
                          + ((lane >> 3) & 1) * 16;

    const int conv_row  = tid >> 2;
    const int conv_koff = (tid & 3) * 32;

    for (int i = 0; i < TILES_PER_CTA; i++) {
        const size_t tile_m = (size_t)(blockIdx.x * TILES_PER_CTA + i) * TM;

        __syncthreads();

        {
            const float4* src = (const float4*)(x + (tile_m + conv_row) * Dsz + conv_koff);
            char* ah = base + OFF_A + conv_row * STRB + conv_koff * 2;
#pragma unroll
            for (int q = 0; q < 8; q++) {
                float4 v = src[q];
                *(uint2*)(ah + q * 8) = make_uint2(h2(v.x, v.y), h2(v.z, v.w));
            }
        }
        __syncthreads();

        float acc[16][4];
#pragma unroll
        for (int j = 0; j < 16; j++)
#pragma unroll
            for (int q = 0; q < 4; q++) acc[j][q] = 0.f;

#pragma unroll
        for (int ks = 0; ks < 8; ks++) {
            uint32_t ra[4];
            ldsm_x4(ra, sA + a_lane + ks * 32);
#pragma unroll
            for (int j = 0; j < 8; j++) {
                uint32_t rb[4];
                ldsm_x4(rb, sB + b_lane + j * (16 * STRB) + ks * 32);
                mma16816(acc[2 * j],     ra, rb[0], rb[1]);
                mma16816(acc[2 * j + 1], ra, rb[2], rb[3]);
            }
        }

        const int g  = lane >> 2;
        const int tc = lane & 3;
        const size_t m0 = tile_m + mrow_off + g;
        const size_t t0 = m0 & 255, b0 = m0 >> 8;
        float* dst0 = g_xproj + (t0 * Bsz + b0) * G4 + ncol_off + 2 * tc;
        float* dst1 = dst0 + 8 * (size_t)Bsz * G4;
#pragma unroll
        for (int j = 0; j < 16; j++) {
            *(float2*)(dst0 + j * 8) = make_float2(acc[j][0], acc[j][1]);
            *(float2*)(dst1 + j * 8) = make_float2(acc[j][2], acc[j][3]);
        }
    }
}

// ===========================================================================
// Kernel B: tensor-core LSTM recurrence, latency-trimmed:
//   - xproj prefetch depth 2 (consume, then reissue same buffer for t+2)
//   - split MMA accumulator chains (kt 0-1 / kt 2-3, add at end)
//   - MUFU tanh.approx pointwise (head sigmoid stays exact)
// ===========================================================================
#define RB   16
#define HSTR 72     // 144 B row stride: 16B-aligned, 4-bank/row shift
#define GSTR 264

#define SM_HA    0
#define SM_OVL   (RB * HSTR * 2)             // 2304
#define SM_TOTAL (SM_OVL + 256 * HSTR * 2)   // 39168

__device__ __forceinline__ float tanhap(float x) {
    float y;
    asm("tanh.approx.f32 %0, %1;" : "=f"(y) : "f"(x));
    return y;
}
__device__ __forceinline__ float sigm_ap(float x) {
    return fmaf(0.5f, tanhap(0.5f * x), 0.5f);
}
__device__ __forceinline__ float sigm_exact(float v) {
    return __fdividef(1.f, 1.f + __expf(-v));
}

__global__ __launch_bounds__(512, 1) void lstm_rec_tc(
    const float* __restrict__ Whh,
    const float* __restrict__ bih, const float* __restrict__ bhh,
    const float* __restrict__ W1, const float* __restrict__ b1,
    const float* __restrict__ W2, const float* __restrict__ b2,
    float* __restrict__ out)
{
    __shared__ __align__(16) char sm[SM_TOTAL];
    __half* hA  = (__half*)(sm + SM_HA);
    __half* WhS = (__half*)(sm + SM_OVL);
    float*  gs  = (float*)(sm + SM_OVL);

    const int tid  = threadIdx.x;
    const int lane = tid & 31;
    const int w    = tid >> 5;
    const int r0   = blockIdx.x * RB;

    // stage Whh fp32 -> fp16 smem
    {
        const int gg   = tid >> 1;
        const int koff = (tid & 1) * 32;
        const float4* src = (const float4*)(Whh + (size_t)gg * Hsz + koff);
        __half* dst = WhS + gg * HSTR + koff;
#pragma unroll
        for (int q = 0; q < 8; q++) {
            float4 v = src[q];
            *(uint2*)(dst + q * 4) = make_uint2(h2(v.x, v.y), h2(v.z, v.w));
        }
    }
    __syncthreads();

    // preload W_hh B fragments
    uint32_t rbf[4][4];
    {
        const uint32_t sW = smem_u32(WhS);
        const uint32_t b_lane = (uint32_t)(16 * w + ((lane >> 4) << 3) + (lane & 7)) * (HSTR * 2)
                              + ((lane >> 3) & 1) * 16;
#pragma unroll
        for (int kt = 0; kt < 4; kt++) ldsm_x4(rbf[kt], sW + b_lane + kt * 32);
    }
    __syncthreads();

    for (int i = tid; i < RB * Hsz; i += 512) hA[(i >> 6) * HSTR + (i & 63)] = __float2half(0.f);

    const int rA  = lane >> 2;
    const int gB0 = 16 * w + 2 * (lane & 3);

    float2 biasv[2];
#pragma unroll
    for (int nt = 0; nt < 2; nt++) {
        int g = gB0 + nt * 8;
        biasv[nt] = make_float2(bih[g] + bhh[g], bih[g + 1] + bhh[g + 1]);
    }

    const size_t baseA0 = (size_t)(r0 + rA) * G4 + gB0;
    const size_t baseB0 = (size_t)(r0 + rA + 8) * G4 + gB0;
    const size_t tstep  = (size_t)Bsz * G4;

    // depth-2 prefetch: buf[t&1] holds step t's fragments
    float2 xbA[2][2], xbB[2][2];
#pragma unroll
    for (int nt = 0; nt < 2; nt++) {
        xbA[0][nt] = *(const float2*)(g_xproj + baseA0 + nt * 8);
        xbB[0][nt] = *(const float2*)(g_xproj + baseB0 + nt * 8);
        xbA[1][nt] = *(const float2*)(g_xproj + tstep + baseA0 + nt * 8);
        xbB[1][nt] = *(const float2*)(g_xproj + tstep + baseB0 + nt * 8);
    }

    const int pr0 = tid >> 6;
    const int pj  = tid & 63;
    float c0 = 0.f, c1 = 0.f;

    const uint32_t sHA    = smem_u32(hA);
    const uint32_t a_lane = (uint32_t)(lane & 15) * (HSTR * 2) + (lane >> 4) * 16;

    __syncthreads();

#pragma unroll 2
    for (int t = 0; t < Tsz; t++) {
        const int cur = t & 1;

        // acc init = bias + xproj (consume buf[cur])
        float accA[2][4], accB[2][4];
#pragma unroll
        for (int nt = 0; nt < 2; nt++) {
            accA[nt][0] = biasv[nt].x + xbA[cur][nt].x;
            accA[nt][1] = biasv[nt].y + xbA[cur][nt].y;
            accA[nt][2] = biasv[nt].x + xbB[cur][nt].x;
            accA[nt][3] = biasv[nt].y + xbB[cur][nt].y;
            accB[nt][0] = 0.f; accB[nt][1] = 0.f;
            accB[nt][2] = 0.f; accB[nt][3] = 0.f;
        }

        // reissue buf[cur] for step t+2 (~2 steps of DRAM slack)
        {
            const size_t tn = (size_t)((t + 2 < Tsz) ? t + 2 : Tsz - 1) * tstep;
#pragma unroll
            for (int nt = 0; nt < 2; nt++) {
                xbA[cur][nt] = *(const float2*)(g_xproj + tn + baseA0 + nt * 8);
                xbB[cur][nt] = *(const float2*)(g_xproj + tn + baseB0 + nt * 8);
            }
        }

        // matvec: two independent 2-deep MMA chains per n-tile
        uint32_t ra0[4], ra1[4], ra2[4], ra3[4];
        ldsm_x4(ra0, sHA + a_lane + 0 * 32);
        ldsm_x4(ra1, sHA + a_lane + 1 * 32);
        ldsm_x4(ra2, sHA + a_lane + 2 * 32);
        ldsm_x4(ra3, sHA + a_lane + 3 * 32);
#pragma unroll
        for (int nt = 0; nt < 2; nt++) {
            mma16816(accA[nt], ra0, rbf[0][2 * nt], rbf[0][2 * nt + 1]);
            mma16816(accB[nt], ra2, rbf[2][2 * nt], rbf[2][2 * nt + 1]);
            mma16816(accA[nt], ra1, rbf[1][2 * nt], rbf[1][2 * nt + 1]);
            mma16816(accB[nt], ra3, rbf[3][2 * nt], rbf[3][2 * nt + 1]);
        }

        // gate exchange
#pragma unroll
        for (int nt = 0; nt < 2; nt++) {
            *(float2*)&gs[rA * GSTR + gB0 + nt * 8] =
                make_float2(accA[nt][0] + accB[nt][0], accA[nt][1] + accB[nt][1]);
            *(float2*)&gs[(rA + 8) * GSTR + gB0 + nt * 8] =
                make_float2(accA[nt][2] + accB[nt][2], accA[nt][3] + accB[nt][3]);
        }
        __syncthreads();

        // pointwise (MUFU tanh.approx)
        {
            float vi = sigm_ap(gs[pr0 * GSTR + pj]);
            float vf = sigm_ap(gs[pr0 * GSTR + 64 + pj]);
            float vg = tanhap(gs[pr0 * GSTR + 128 + pj]);
            float vo = sigm_ap(gs[pr0 * GSTR + 192 + pj]);
            c0 = vf * c0 + vi * vg;
            hA[pr0 * HSTR + pj] = __float2half(vo * tanhap(c0));
        }
        {
            const int pr1 = pr0 + 8;
            float vi = sigm_ap(gs[pr1 * GSTR + pj]);
            float vf = sigm_ap(gs[pr1 * GSTR + 64 + pj]);
            float vg = tanhap(gs[pr1 * GSTR + 128 + pj]);
            float vo = sigm_ap(gs[pr1 * GSTR + 192 + pj]);
            c1 = vf * c1 + vi * vg;
            hA[pr1 * HSTR + pj] = __float2half(vo * tanhap(c1));
        }
        __syncthreads();
    }

    // fused head (exact sigmoid — undamped path)
    {
        float y1 = b1[lane];
#pragma unroll
        for (int k = 0; k < Hsz; k++)
            y1 += W1[lane * Hsz + k] * __half2float(hA[w * HSTR + k]);
        y1 = fmaxf(y1, 0.f);
        float z = y1 * W2[lane];
#pragma unroll
        for (int off = 16; off > 0; off >>= 1) z += __shfl_down_sync(0xffffffffu, z, off);
        if (lane == 0) out[r0 + w] = sigm_exact(z + b2[0]);
    }
}

// ===========================================================================
extern "C" void kernel_launch(void* const* d_in, const int* in_sizes, int n_in,
                              void* d_out, int out_size)
{
    const float* x   = (const float*)d_in[0];
    const float* Wih = (const float*)d_in[1];
    const float* Whh = (const float*)d_in[2];
    const float* bih = (const float*)d_in[3];
    const float* bhh = (const float*)d_in[4];
    const float* W1  = (const float*)d_in[5];
    const float* b1  = (const float*)d_in[6];
    const float* W2  = (const float*)d_in[7];
    const float* b2  = (const float*)d_in[8];
    float* out = (float*)d_out;

    static bool attr_set = false;
    if (!attr_set) {
        cudaFuncSetAttribute(xproj_tc, cudaFuncAttributeMaxDynamicSharedMemorySize, GEMM_SMEM);
        attr_set = true;
    }
    xproj_tc<<<GEMM_CTAS, 512, GEMM_SMEM>>>(x, Wih);
    lstm_rec_tc<<<Bsz / RB, 512>>>(Whh, bih, bhh, W1, b1, W2, b2, out);
}

// round 12
// speedup vs baseline: 2.5089x; 1.0215x over previous
#include <cuda_runtime.h>
#include <cuda_fp16.h>
#include <cstdint>

#define Bsz 1024
#define Tsz 256
#define Dsz 128
#define Hsz 64
#define G4  256   // 4*H

// 256 MB scratch, layout [t][b][g_permuted]
__device__ float g_xproj[Tsz * Bsz * G4];

// permuted col p -> original gate row
__device__ __host__ __forceinline__ int orig_gate(int p) {
    int w_  = p >> 5;
    int nt_ = (p >> 3) & 3;
    int lc_ = p & 7;
    return 64 * (lc_ & 3) + 8 * w_ + 2 * nt_ + (lc_ >> 2);
}

__device__ __forceinline__ uint32_t smem_u32(const void* p) {
    uint32_t a;
    asm("{ .reg .u64 t; cvta.to.shared.u64 t, %1; cvt.u32.u64 %0, t; }"
        : "=r"(a) : "l"(p));
    return a;
}

__device__ __forceinline__ void ldsm_x4(uint32_t* r, uint32_t addr) {
    asm volatile("ldmatrix.sync.aligned.m8n8.x4.shared.b16 {%0,%1,%2,%3}, [%4];"
                 : "=r"(r[0]), "=r"(r[1]), "=r"(r[2]), "=r"(r[3]) : "r"(addr));
}

__device__ __forceinline__ void mma16816(float* d, const uint32_t* a,
                                         uint32_t b0, uint32_t b1) {
    asm volatile(
        "mma.sync.aligned.m16n8k16.row.col.f32.f16.f16.f32 "
        "{%0,%1,%2,%3}, {%4,%5,%6,%7}, {%8,%9}, {%0,%1,%2,%3};"
        : "+f"(d[0]), "+f"(d[1]), "+f"(d[2]), "+f"(d[3])
        : "r"(a[0]), "r"(a[1]), "r"(a[2]), "r"(a[3]), "r"(b0), "r"(b1));
}

__device__ __forceinline__ uint32_t h2(float a, float b) {
    __half2 h = __floats2half2_rn(a, b);
    return *(uint32_t*)&h;
}

// ===========================================================================
// Kernel A: x_proj = x @ W_ih^T (permuted gate cols), single-pass fp16 HMMA.
// ===========================================================================
#define GEMM_CTAS     512
#define TILES_PER_CTA 4
#define TM 128
#define STRB 272
#define A_BYTES (128 * STRB)
#define B_BYTES (256 * STRB)
#define OFF_A 0
#define OFF_B (A_BYTES)
#define GEMM_SMEM (A_BYTES + B_BYTES + 1024)

__global__ __launch_bounds__(512, 1) void xproj_tc(
    const float* __restrict__ x,
    const float* __restrict__ Wih)
{
    extern __shared__ char dyn[];
    char* base = (char*)(((uintptr_t)dyn + 1023) & ~(uintptr_t)1023);

    const int tid  = threadIdx.x;
    const int lane = tid & 31;
    const int warp = tid >> 5;
    const int mrow_off = (warp & 7) * 16;
    const int ncol_off = (warp >> 3) * 128;

    // convert B (Wih fp32 -> fp16 smem), rows permuted: smem row p = Wih[orig(p)]
    {
        const int row  = tid >> 1;            // permuted index p
        const int koff = (tid & 1) * 64;
        const int og   = orig_gate(row);
        const float4* src = (const float4*)(Wih + (size_t)og * Dsz + koff);
        char* bh = base + OFF_B + row * STRB + koff * 2;
#pragma unroll
        for (int q = 0; q < 16; q++) {
            float4 v = src[q];
            *(uint2*)(bh + q * 8) = make_uint2(h2(v.x, v.y), h2(v.z, v.w));
        }
    }

    const uint32_t sA = smem_u32(base + OFF_A);
    const uint32_t sB = smem_u32(base + OFF_B);

    const uint32_t a_lane = (uint32_t)(mrow_off + (lane & 15)) * STRB + (lane >> 4) * 16;
    const uint32_t b_lane = (uint32_t)(ncol_off + ((lane >> 4) << 3) + (lane & 7)) * STRB
                          + ((lane >> 3) & 1) * 16;

    const int conv_row  = tid >> 2;
    const int conv_koff = (tid & 3) * 32;

    for (int i = 0; i < TILES_PER_CTA; i++) {
        const size_t tile_m = (size_t)(blockIdx.x * TILES_PER_CTA + i) * TM;

        __syncthreads();

        {
            const float4* src = (const float4*)(x + (tile_m + conv_row) * Dsz + conv_koff);
            char* ah = base + OFF_A + conv_row * STRB + conv_koff * 2;
#pragma unroll
            for (int q = 0; q < 8; q++) {
                float4 v = src[q];
                *(uint2*)(ah + q * 8) = make_uint2(h2(v.x, v.y), h2(v.z, v.w));
            }
        }
        __syncthreads();

        float acc[16][4];
#pragma unroll
        for (int j = 0; j < 16; j++)
#pragma unroll
            for (int q = 0; q < 4; q++) acc[j][q] = 0.f;

#pragma unroll
        for (int ks = 0; ks < 8; ks++) {
            uint32_t ra[4];
            ldsm_x4(ra, sA + a_lane + ks * 32);
#pragma unroll
            for (int j = 0; j < 8; j++) {
                uint32_t rb[4];
                ldsm_x4(rb, sB + b_lane + j * (16 * STRB) + ks * 32);
                mma16816(acc[2 * j],     ra, rb[0], rb[1]);
                mma16816(acc[2 * j + 1], ra, rb[2], rb[3]);
            }
        }

        const int g  = lane >> 2;
        const int tc = lane & 3;
        const size_t m0 = tile_m + mrow_off + g;
        const size_t t0 = m0 & 255, b0 = m0 >> 8;
        float* dst0 = g_xproj + (t0 * Bsz + b0) * G4 + ncol_off + 2 * tc;
        float* dst1 = dst0 + 8 * (size_t)Bsz * G4;
#pragma unroll
        for (int j = 0; j < 16; j++) {
            *(float2*)(dst0 + j * 8) = make_float2(acc[j][0], acc[j][1]);
            *(float2*)(dst1 + j * 8) = make_float2(acc[j][2], acc[j][3]);
        }
    }
}

// ===========================================================================
// Kernel B: tensor-core LSTM recurrence with permuted gate columns.
// 64 blocks x 256 threads (8 warps). Warp w owns permuted cols 32w..32w+31 =
// all 4 gate types for units 8w+2nt+m. Pointwise is intra-warp (shfl.xor(1)),
// h double-buffered -> ONE __syncthreads per step. h carried fp16.
// ===========================================================================
#define RB   16
#define HSTR 72                       // 144B row stride (16B-aligned, 4-bank shift)
#define HBUFB (RB * HSTR * 2)         // bytes per h buffer = 2304

#define SM_HA    0
#define SM_WHS   (2 * HBUFB)          // 4608
#define SM_TOTAL (SM_WHS + 256 * HSTR * 2)   // 4608 + 36864 = 41472

__device__ __forceinline__ float tanhap(float x) {
    float y;
    asm("tanh.approx.f32 %0, %1;" : "=f"(y) : "f"(x));
    return y;
}
__device__ __forceinline__ float sigm_ap(float x) {
    return fmaf(0.5f, tanhap(0.5f * x), 0.5f);
}
__device__ __forceinline__ float sigm_exact(float v) {
    return __fdividef(1.f, 1.f + __expf(-v));
}

__global__ __launch_bounds__(256, 1) void lstm_rec_tc(
    const float* __restrict__ Whh,
    const float* __restrict__ bih, const float* __restrict__ bhh,
    const float* __restrict__ W1, const float* __restrict__ b1,
    const float* __restrict__ W2, const float* __restrict__ b2,
    float* __restrict__ out)
{
    __shared__ __align__(16) char sm[SM_TOTAL];
    __half* hA  = (__half*)(sm + SM_HA);     // [2][RB][HSTR]
    __half* WhS = (__half*)(sm + SM_WHS);    // [256][HSTR] permuted Whh

    const int tid  = threadIdx.x;
    const int lane = tid & 31;
    const int w    = tid >> 5;               // warp 0..7
    const int rq   = lane >> 2;              // r' 0..7
    const int q    = lane & 3;
    const bool even = (q & 1) == 0;
    const int r0   = blockIdx.x * RB;

    // ---- stage permuted Whh fp32 -> fp16 smem (row p = Whh[orig(p)]) ----
    {
        const int p  = tid;                  // 0..255
        const int og = orig_gate(p);
        const float4* src = (const float4*)(Whh + (size_t)og * Hsz);
        __half* dst = WhS + p * HSTR;
#pragma unroll
        for (int qq = 0; qq < 16; qq++) {
            float4 v = src[qq];
            *(uint2*)(dst + qq * 4) = make_uint2(h2(v.x, v.y), h2(v.z, v.w));
        }
    }
    __syncthreads();

    // ---- preload B fragments: 4 kt x 4 n-tiles (2 regs each) ----
    uint32_t rbf[4][8];   // [kt][nt*2 + {0,1}]
    {
        const uint32_t sW = smem_u32(WhS);
        const uint32_t bl1 = (uint32_t)(32 * w + ((lane >> 4) << 3) + (lane & 7)) * (HSTR * 2)
                           + ((lane >> 3) & 1) * 16;
        const uint32_t bl2 = bl1 + 16 * (HSTR * 2);
#pragma unroll
        for (int kt = 0; kt < 4; kt++) {
            uint32_t r1[4], r2[4];
            ldsm_x4(r1, sW + bl1 + kt * 32);
            ldsm_x4(r2, sW + bl2 + kt * 32);
            rbf[kt][0] = r1[0]; rbf[kt][1] = r1[1];
            rbf[kt][2] = r1[2]; rbf[kt][3] = r1[3];
            rbf[kt][4] = r2[0]; rbf[kt][5] = r2[1];
            rbf[kt][6] = r2[2]; rbf[kt][7] = r2[3];
        }
    }

    // ---- zero both h buffers ----
    for (int i = tid; i < 2 * RB * HSTR; i += 256) hA[i] = __float2half(0.f);

    // ---- bias fragments (per D col, permuted index -> orig) ----
    float2 biasv[4];
#pragma unroll
    for (int nt = 0; nt < 4; nt++) {
        int p0 = 32 * w + 8 * nt + 2 * q;
        biasv[nt] = make_float2(bih[orig_gate(p0)] + bhh[orig_gate(p0)],
                                bih[orig_gate(p0 + 1)] + bhh[orig_gate(p0 + 1)]);
    }

    // ---- xproj bases ----
    const size_t tstep  = (size_t)Bsz * G4;
    const size_t baseA0 = (size_t)(r0 + rq) * G4 + 32 * w + 2 * q;       // + nt*8
    const size_t baseB0 = (size_t)(r0 + rq + 8) * G4 + 32 * w + 2 * q;

    // depth-2 prefetch buffers
    float2 xbA[2][4], xbB[2][4];
#pragma unroll
    for (int nt = 0; nt < 4; nt++) {
        xbA[0][nt] = *(const float2*)(g_xproj + baseA0 + nt * 8);
        xbB[0][nt] = *(const float2*)(g_xproj + baseB0 + nt * 8);
        xbA[1][nt] = *(const float2*)(g_xproj + tstep + baseA0 + nt * 8);
        xbB[1][nt] = *(const float2*)(g_xproj + tstep + baseB0 + nt * 8);
    }

    float c[4] = {0.f, 0.f, 0.f, 0.f};

    const uint32_t sHA = smem_u32(hA);
    const uint32_t a_lane_base = (uint32_t)(lane & 15) * (HSTR * 2) + (lane >> 4) * 16;

    // pointwise cell coords: row (even? rq : rq+8), unit 8w + 2nt + (q>>1)
    const int prow  = even ? rq : rq + 8;
    const int ubase = 8 * w + (q >> 1);

    __syncthreads();

#pragma unroll 2
    for (int t = 0; t < Tsz; t++) {
        const int cur = t & 1;

        // acc init = bias + xproj
        float acc[4][4];
#pragma unroll
        for (int nt = 0; nt < 4; nt++) {
            acc[nt][0] = biasv[nt].x + xbA[cur][nt].x;
            acc[nt][1] = biasv[nt].y + xbA[cur][nt].y;
            acc[nt][2] = biasv[nt].x + xbB[cur][nt].x;
            acc[nt][3] = biasv[nt].y + xbB[cur][nt].y;
        }

        // reissue buf[cur] for t+2
        {
            const size_t tn = (size_t)((t + 2 < Tsz) ? t + 2 : Tsz - 1) * tstep;
#pragma unroll
            for (int nt = 0; nt < 4; nt++) {
                xbA[cur][nt] = *(const float2*)(g_xproj + tn + baseA0 + nt * 8);
                xbB[cur][nt] = *(const float2*)(g_xproj + tn + baseB0 + nt * 8);
            }
        }

        // matvec: h (fp16, buf cur) @ Whh-permuted; 4 indep chains of depth 4
        const uint32_t aL = sHA + cur * HBUFB + a_lane_base;
        uint32_t ra[4][4];
        ldsm_x4(ra[0], aL + 0 * 32);
        ldsm_x4(ra[1], aL + 1 * 32);
        ldsm_x4(ra[2], aL + 2 * 32);
        ldsm_x4(ra[3], aL + 3 * 32);
#pragma unroll
        for (int kt = 0; kt < 4; kt++) {
            mma16816(acc[0], ra[kt], rbf[kt][0], rbf[kt][1]);
            mma16816(acc[1], ra[kt], rbf[kt][2], rbf[kt][3]);
            mma16816(acc[2], ra[kt], rbf[kt][4], rbf[kt][5]);
            mma16816(acc[3], ra[kt], rbf[kt][6], rbf[kt][7]);
        }

        // intra-warp gate exchange + pointwise; write h to buf nxt
        __half* hnext = (__half*)(sm + SM_HA + ((t + 1) & 1) * HBUFB);
#pragma unroll
        for (int nt = 0; nt < 4; nt++) {
            float s1 = even ? acc[nt][2] : acc[nt][0];   // even sends i(r'+8); odd sends g(r')
            float r1 = __shfl_xor_sync(0xffffffffu, s1, 1);
            float s2 = even ? acc[nt][3] : acc[nt][1];   // even sends f(r'+8); odd sends o(r')
            float r2 = __shfl_xor_sync(0xffffffffu, s2, 1);

            float vi = even ? acc[nt][0] : r1;
            float vf = even ? acc[nt][1] : r2;
            float vg = even ? r1 : acc[nt][2];
            float vo = even ? r2 : acc[nt][3];

            vi = sigm_ap(vi);
            vf = sigm_ap(vf);
            vg = tanhap(vg);
            vo = sigm_ap(vo);
            c[nt] = fmaf(vf, c[nt], vi * vg);
            float hv = vo * tanhap(c[nt]);

            hnext[prow * HSTR + ubase + 2 * nt] = __float2half(hv);
        }
        __syncthreads();
    }

    // ---- fused head: final h in buf[Tsz & 1] = buf 0; warp w rows w, w+8 ----
    {
        __half* hfin = (__half*)(sm + SM_HA + (Tsz & 1) * HBUFB);
#pragma unroll
        for (int rr = w; rr < RB; rr += 8) {
            float y1 = b1[lane];
#pragma unroll
            for (int k = 0; k < Hsz; k++)
                y1 += W1[lane * Hsz + k] * __half2float(hfin[rr * HSTR + k]);
            y1 = fmaxf(y1, 0.f);
            float z = y1 * W2[lane];
#pragma unroll
            for (int off = 16; off > 0; off >>= 1) z += __shfl_down_sync(0xffffffffu, z, off);
            if (lane == 0) out[r0 + rr] = sigm_exact(z + b2[0]);
        }
    }
}

// ===========================================================================
extern "C" void kernel_launch(void* const* d_in, const int* in_sizes, int n_in,
                              void* d_out, int out_size)
{
    const float* x   = (const float*)d_in[0];
    const float* Wih = (const float*)d_in[1];
    const float* Whh = (const float*)d_in[2];
    const float* bih = (const float*)d_in[3];
    const float* bhh = (const float*)d_in[4];
    const float* W1  = (const float*)d_in[5];
    const float* b1  = (const float*)d_in[6];
    const float* W2  = (const float*)d_in[7];
    const float* b2  = (const float*)d_in[8];
    float* out = (float*)d_out;

    static bool attr_set = false;
    if (!attr_set) {
        cudaFuncSetAttribute(xproj_tc, cudaFuncAttributeMaxDynamicSharedMemorySize, GEMM_SMEM);
        attr_set = true;
    }
    xproj_tc<<<GEMM_CTAS, 512, GEMM_SMEM>>>(x, Wih);
    lstm_rec_tc<<<Bsz / RB, 256>>>(Whh, bih, bhh, W1, b1, W2, b2, out);
}

// round 13
// speedup vs baseline: 2.9328x; 1.1690x over previous
#include <cuda_runtime.h>
#include <cuda_fp16.h>
#include <cstdint>

#define Bsz 1024
#define Tsz 256
#define Dsz 128
#define Hsz 64
#define G4  256   // 4*H

// 128 MB fp16 scratch, layout [t][b][g_permuted]
__device__ __half g_xp16[Tsz * Bsz * G4];

// permuted col p -> original gate row
__device__ __host__ __forceinline__ int orig_gate(int p) {
    int w_  = p >> 5;
    int nt_ = (p >> 3) & 3;
    int lc_ = p & 7;
    return 64 * (lc_ & 3) + 8 * w_ + 2 * nt_ + (lc_ >> 2);
}

__device__ __forceinline__ uint32_t smem_u32(const void* p) {
    uint32_t a;
    asm("{ .reg .u64 t; cvta.to.shared.u64 t, %1; cvt.u32.u64 %0, t; }"
        : "=r"(a) : "l"(p));
    return a;
}

__device__ __forceinline__ void ldsm_x4(uint32_t* r, uint32_t addr) {
    asm volatile("ldmatrix.sync.aligned.m8n8.x4.shared.b16 {%0,%1,%2,%3}, [%4];"
                 : "=r"(r[0]), "=r"(r[1]), "=r"(r[2]), "=r"(r[3]) : "r"(addr));
}

__device__ __forceinline__ void mma16816(float* d, const uint32_t* a,
                                         uint32_t b0, uint32_t b1) {
    asm volatile(
        "mma.sync.aligned.m16n8k16.row.col.f32.f16.f16.f32 "
        "{%0,%1,%2,%3}, {%4,%5,%6,%7}, {%8,%9}, {%0,%1,%2,%3};"
        : "+f"(d[0]), "+f"(d[1]), "+f"(d[2]), "+f"(d[3])
        : "r"(a[0]), "r"(a[1]), "r"(a[2]), "r"(a[3]), "r"(b0), "r"(b1));
}

__device__ __forceinline__ uint32_t h2(float a, float b) {
    __half2 h = __floats2half2_rn(a, b);
    return *(uint32_t*)&h;
}

// ===========================================================================
// Kernel A: x_proj = x @ W_ih^T (permuted cols), fp16 HMMA, fp16 output,
// smem-staged fully-coalesced stores. 1024 CTAs x 2 tiles.
// ===========================================================================
#define GEMM_CTAS     1024
#define TILES_PER_CTA 2
#define TM 128
#define STRB 272
#define A_BYTES (128 * STRB)           // 34816
#define B_BYTES (256 * STRB)           // 69632
#define OFF_A 0
#define OFF_B (A_BYTES)
#define OFF_ST (A_BYTES + B_BYTES)     // 104448 (16B aligned)
#define STG_STR 264                    // halves per stage row (528 B: 132 words ≡ 4 mod 32)
#define STAGE_BYTES (128 * STG_STR * 2)  // 67584
#define GEMM_SMEM (OFF_ST + STAGE_BYTES + 64)

__global__ __launch_bounds__(512, 1) void xproj_tc(
    const float* __restrict__ x,
    const float* __restrict__ Wih)
{
    extern __shared__ char dyn[];
    char* base = (char*)(((uintptr_t)dyn + 1023) & ~(uintptr_t)1023);

    const int tid  = threadIdx.x;
    const int lane = tid & 31;
    const int warp = tid >> 5;
    const int mrow_off = (warp & 7) * 16;
    const int ncol_off = (warp >> 3) * 128;

    // convert B (Wih fp32 -> fp16 smem), rows permuted: smem row p = Wih[orig(p)]
    {
        const int row  = tid >> 1;
        const int koff = (tid & 1) * 64;
        const int og   = orig_gate(row);
        const float4* src = (const float4*)(Wih + (size_t)og * Dsz + koff);
        char* bh = base + OFF_B + row * STRB + koff * 2;
#pragma unroll
        for (int q = 0; q < 16; q++) {
            float4 v = src[q];
            *(uint2*)(bh + q * 8) = make_uint2(h2(v.x, v.y), h2(v.z, v.w));
        }
    }

    const uint32_t sA = smem_u32(base + OFF_A);
    const uint32_t sB = smem_u32(base + OFF_B);
    __half* stg = (__half*)(base + OFF_ST);

    const uint32_t a_lane = (uint32_t)(mrow_off + (lane & 15)) * STRB + (lane >> 4) * 16;
    const uint32_t b_lane = (uint32_t)(ncol_off + ((lane >> 4) << 3) + (lane & 7)) * STRB
                          + ((lane >> 3) & 1) * 16;

    const int conv_row  = tid >> 2;
    const int conv_koff = (tid & 3) * 32;

    for (int i = 0; i < TILES_PER_CTA; i++) {
        const size_t tile_m = (size_t)(blockIdx.x * TILES_PER_CTA + i) * TM;

        __syncthreads();   // prev tile fully consumed (stage written out, A free)

        // convert A tile (128x128 fp32 -> fp16 smem)
        {
            const float4* src = (const float4*)(x + (tile_m + conv_row) * Dsz + conv_koff);
            char* ah = base + OFF_A + conv_row * STRB + conv_koff * 2;
#pragma unroll
            for (int q = 0; q < 8; q++) {
                float4 v = src[q];
                *(uint2*)(ah + q * 8) = make_uint2(h2(v.x, v.y), h2(v.z, v.w));
            }
        }
        __syncthreads();

        float acc[16][4];
#pragma unroll
        for (int j = 0; j < 16; j++)
#pragma unroll
            for (int q = 0; q < 4; q++) acc[j][q] = 0.f;

#pragma unroll
        for (int ks = 0; ks < 8; ks++) {
            uint32_t ra[4];
            ldsm_x4(ra, sA + a_lane + ks * 32);
#pragma unroll
            for (int j = 0; j < 8; j++) {
                uint32_t rb[4];
                ldsm_x4(rb, sB + b_lane + j * (16 * STRB) + ks * 32);
                mma16816(acc[2 * j],     ra, rb[0], rb[1]);
                mma16816(acc[2 * j + 1], ra, rb[2], rb[3]);
            }
        }

        // ---- stage acc -> fp16 smem (conflict-free: banks 4g+tc) ----
        {
            const int g  = lane >> 2;
            const int tc = lane & 3;
            const int r_lo = mrow_off + g;
            const int r_hi = r_lo + 8;
#pragma unroll
            for (int j = 0; j < 16; j++) {
                const int col = ncol_off + 2 * tc + 8 * j;
                *(__half2*)(stg + r_lo * STG_STR + col) =
                    __floats2half2_rn(acc[j][0], acc[j][1]);
                *(__half2*)(stg + r_hi * STG_STR + col) =
                    __floats2half2_rn(acc[j][2], acc[j][3]);
            }
        }
        __syncthreads();

        // ---- coalesced write-out: warp w handles rows 8w..8w+7 (512B each) ----
        {
            const int b_idx  = (int)(tile_m >> 8);
            const int t_base = (int)(tile_m & 255);
#pragma unroll
            for (int r = 0; r < 8; r++) {
                const int sr = 8 * warp + r;
                __half* dst = g_xp16 + ((size_t)(t_base + sr) * Bsz + b_idx) * G4;
                uint4 v = *(const uint4*)(stg + sr * STG_STR + lane * 8);
                *(uint4*)(dst + lane * 8) = v;
            }
        }
    }
}

// ===========================================================================
// Kernel B: tensor-core LSTM recurrence (permuted gates, intra-warp exchange,
// one barrier/step, fp16 h AND fp16 xproj loads). 64 blocks x 256 threads.
// ===========================================================================
#define RB   16
#define HSTR 72                       // 144B row stride (16B-aligned, 4-bank shift)
#define HBUFB (RB * HSTR * 2)         // 2304

#define SM_HA    0
#define SM_WHS   (2 * HBUFB)          // 4608
#define SM_TOTAL (SM_WHS + 256 * HSTR * 2)   // 41472

__device__ __forceinline__ float tanhap(float x) {
    float y;
    asm("tanh.approx.f32 %0, %1;" : "=f"(y) : "f"(x));
    return y;
}
__device__ __forceinline__ float sigm_ap(float x) {
    return fmaf(0.5f, tanhap(0.5f * x), 0.5f);
}
__device__ __forceinline__ float sigm_exact(float v) {
    return __fdividef(1.f, 1.f + __expf(-v));
}

__global__ __launch_bounds__(256, 1) void lstm_rec_tc(
    const float* __restrict__ Whh,
    const float* __restrict__ bih, const float* __restrict__ bhh,
    const float* __restrict__ W1, const float* __restrict__ b1,
    const float* __restrict__ W2, const float* __restrict__ b2,
    float* __restrict__ out)
{
    __shared__ __align__(16) char sm[SM_TOTAL];
    __half* hA  = (__half*)(sm + SM_HA);     // [2][RB][HSTR]
    __half* WhS = (__half*)(sm + SM_WHS);    // [256][HSTR] permuted Whh

    const int tid  = threadIdx.x;
    const int lane = tid & 31;
    const int w    = tid >> 5;
    const int rq   = lane >> 2;
    const int q    = lane & 3;
    const bool even = (q & 1) == 0;
    const int r0   = blockIdx.x * RB;

    // stage permuted Whh fp32 -> fp16 smem
    {
        const int p  = tid;
        const int og = orig_gate(p);
        const float4* src = (const float4*)(Whh + (size_t)og * Hsz);
        __half* dst = WhS + p * HSTR;
#pragma unroll
        for (int qq = 0; qq < 16; qq++) {
            float4 v = src[qq];
            *(uint2*)(dst + qq * 4) = make_uint2(h2(v.x, v.y), h2(v.z, v.w));
        }
    }
    __syncthreads();

    // preload B fragments: 4 kt x 4 n-tiles
    uint32_t rbf[4][8];
    {
        const uint32_t sW = smem_u32(WhS);
        const uint32_t bl1 = (uint32_t)(32 * w + ((lane >> 4) << 3) + (lane & 7)) * (HSTR * 2)
                           + ((lane >> 3) & 1) * 16;
        const uint32_t bl2 = bl1 + 16 * (HSTR * 2);
#pragma unroll
        for (int kt = 0; kt < 4; kt++) {
            uint32_t r1[4], r2[4];
            ldsm_x4(r1, sW + bl1 + kt * 32);
            ldsm_x4(r2, sW + bl2 + kt * 32);
            rbf[kt][0] = r1[0]; rbf[kt][1] = r1[1];
            rbf[kt][2] = r1[2]; rbf[kt][3] = r1[3];
            rbf[kt][4] = r2[0]; rbf[kt][5] = r2[1];
            rbf[kt][6] = r2[2]; rbf[kt][7] = r2[3];
        }
    }

    for (int i = tid; i < 2 * RB * HSTR; i += 256) hA[i] = __float2half(0.f);

    // bias fragments
    float2 biasv[4];
#pragma unroll
    for (int nt = 0; nt < 4; nt++) {
        int p0 = 32 * w + 8 * nt + 2 * q;
        biasv[nt] = make_float2(bih[orig_gate(p0)] + bhh[orig_gate(p0)],
                                bih[orig_gate(p0 + 1)] + bhh[orig_gate(p0 + 1)]);
    }

    // xproj bases (half-element indices)
    const size_t tstep  = (size_t)Bsz * G4;
    const size_t baseA0 = (size_t)(r0 + rq) * G4 + 32 * w + 2 * q;
    const size_t baseB0 = (size_t)(r0 + rq + 8) * G4 + 32 * w + 2 * q;

    // depth-2 prefetch buffers (raw half2 in uint32)
    uint32_t xbA[2][4], xbB[2][4];
#pragma unroll
    for (int nt = 0; nt < 4; nt++) {
        xbA[0][nt] = *(const uint32_t*)(g_xp16 + baseA0 + nt * 8);
        xbB[0][nt] = *(const uint32_t*)(g_xp16 + baseB0 + nt * 8);
        xbA[1][nt] = *(const uint32_t*)(g_xp16 + tstep + baseA0 + nt * 8);
        xbB[1][nt] = *(const uint32_t*)(g_xp16 + tstep + baseB0 + nt * 8);
    }

    float c[4] = {0.f, 0.f, 0.f, 0.f};

    const uint32_t sHA = smem_u32(hA);
    const uint32_t a_lane_base = (uint32_t)(lane & 15) * (HSTR * 2) + (lane >> 4) * 16;

    const int prow  = even ? rq : rq + 8;
    const int ubase = 8 * w + (q >> 1);

    __syncthreads();

#pragma unroll 2
    for (int t = 0; t < Tsz; t++) {
        const int cur = t & 1;

        // acc init = bias + xproj (convert half2 -> float2)
        float acc[4][4];
#pragma unroll
        for (int nt = 0; nt < 4; nt++) {
            float2 xa = __half22float2(*(__half2*)&xbA[cur][nt]);
            float2 xb = __half22float2(*(__half2*)&xbB[cur][nt]);
            acc[nt][0] = biasv[nt].x + xa.x;
            acc[nt][1] = biasv[nt].y + xa.y;
            acc[nt][2] = biasv[nt].x + xb.x;
            acc[nt][3] = biasv[nt].y + xb.y;
        }

        // reissue buf[cur] for t+2
        {
            const size_t tn = (size_t)((t + 2 < Tsz) ? t + 2 : Tsz - 1) * tstep;
#pragma unroll
            for (int nt = 0; nt < 4; nt++) {
                xbA[cur][nt] = *(const uint32_t*)(g_xp16 + tn + baseA0 + nt * 8);
                xbB[cur][nt] = *(const uint32_t*)(g_xp16 + tn + baseB0 + nt * 8);
            }
        }

        // matvec
        const uint32_t aL = sHA + cur * HBUFB + a_lane_base;
        uint32_t ra[4][4];
        ldsm_x4(ra[0], aL + 0 * 32);
        ldsm_x4(ra[1], aL + 1 * 32);
        ldsm_x4(ra[2], aL + 2 * 32);
        ldsm_x4(ra[3], aL + 3 * 32);
#pragma unroll
        for (int kt = 0; kt < 4; kt++) {
            mma16816(acc[0], ra[kt], rbf[kt][0], rbf[kt][1]);
            mma16816(acc[1], ra[kt], rbf[kt][2], rbf[kt][3]);
            mma16816(acc[2], ra[kt], rbf[kt][4], rbf[kt][5]);
            mma16816(acc[3], ra[kt], rbf[kt][6], rbf[kt][7]);
        }

        // intra-warp gate exchange + pointwise; write h to buf nxt
        __half* hnext = (__half*)(sm + SM_HA + ((t + 1) & 1) * HBUFB);
#pragma unroll
        for (int nt = 0; nt < 4; nt++) {
            float s1 = even ? acc[nt][2] : acc[nt][0];
            float r1 = __shfl_xor_sync(0xffffffffu, s1, 1);
            float s2 = even ? acc[nt][3] : acc[nt][1];
            float r2 = __shfl_xor_sync(0xffffffffu, s2, 1);

            float vi = even ? acc[nt][0] : r1;
            float vf = even ? acc[nt][1] : r2;
            float vg = even ? r1 : acc[nt][2];
            float vo = even ? r2 : acc[nt][3];

            vi = sigm_ap(vi);
            vf = sigm_ap(vf);
            vg = tanhap(vg);
            vo = sigm_ap(vo);
            c[nt] = fmaf(vf, c[nt], vi * vg);
            float hv = vo * tanhap(c[nt]);

            hnext[prow * HSTR + ubase + 2 * nt] = __float2half(hv);
        }
        __syncthreads();
    }

    // fused head (exact sigmoid)
    {
        __half* hfin = (__half*)(sm + SM_HA + (Tsz & 1) * HBUFB);
#pragma unroll
        for (int rr = w; rr < RB; rr += 8) {
            float y1 = b1[lane];
#pragma unroll
            for (int k = 0; k < Hsz; k++)
                y1 += W1[lane * Hsz + k] * __half2float(hfin[rr * HSTR + k]);
            y1 = fmaxf(y1, 0.f);
            float z = y1 * W2[lane];
#pragma unroll
            for (int off = 16; off > 0; off >>= 1) z += __shfl_down_sync(0xffffffffu, z, off);
            if (lane == 0) out[r0 + rr] = sigm_exact(z + b2[0]);
        }
    }
}

// ===========================================================================
extern "C" void kernel_launch(void* const* d_in, const int* in_sizes, int n_in,
                              void* d_out, int out_size)
{
    const float* x   = (const float*)d_in[0];
    const float* Wih = (const float*)d_in[1];
    const float* Whh = (const float*)d_in[2];
    const float* bih = (const float*)d_in[3];
    const float* bhh = (const float*)d_in[4];
    const float* W1  = (const float*)d_in[5];
    const float* b1  = (const float*)d_in[6];
    const float* W2  = (const float*)d_in[7];
    const float* b2  = (const float*)d_in[8];
    float* out = (float*)d_out;

    static bool attr_set = false;
    if (!attr_set) {
        cudaFuncSetAttribute(xproj_tc, cudaFuncAttributeMaxDynamicSharedMemorySize, GEMM_SMEM);
        attr_set = true;
    }
    xproj_tc<<<GEMM_CTAS, 512, GEMM_SMEM>>>(x, Wih);
    lstm_rec_tc<<<Bsz / RB, 256>>>(Whh, bih, bhh, W1, b1, W2, b2, out);
}